// round 2
// baseline (speedup 1.0000x reference)
#include <cuda_runtime.h>

// field[i,j] = sum_n w_n * ox_n[i] * oy_n[j] / (lx*ly)
// Each rect has dims <= 3/G, so it overlaps at most 4 consecutive cells per axis.
// Scatter with global float atomics.

#define G 256

__global__ void zero_field_kernel(float* __restrict__ out, int n) {
    int i = blockIdx.x * blockDim.x + threadIdx.x;
    if (i < n) out[i] = 0.0f;
}

__global__ void __launch_bounds__(256) charge_scatter_kernel(
    const float* __restrict__ boundary,   // [xmin, ymin, xmax, ymax]
    const float2* __restrict__ xy,        // [N]
    const float2* __restrict__ dims,      // [N]
    const float* __restrict__ cw,         // [N]
    float* __restrict__ field,            // [G*G]
    int n)
{
    int t = blockIdx.x * blockDim.x + threadIdx.x;
    if (t >= n) return;

    const float xmin = boundary[0];
    const float ymin = boundary[1];
    const float xmax = boundary[2];
    const float ymax = boundary[3];
    const float lx = (xmax - xmin) * (1.0f / G);
    const float ly = (ymax - ymin) * (1.0f / G);
    const float inv_lx = 1.0f / lx;
    const float inv_ly = 1.0f / ly;

    const float2 p = xy[t];
    const float2 d = dims[t];
    const float bx0 = p.x;
    const float by0 = p.y;
    const float bx1 = bx0 + d.x;
    const float by1 = by0 + d.y;
    const float scale = cw[t] * inv_lx * inv_ly;

    // Cell index ranges touched (clamped to grid)
    int i0 = (int)floorf((bx0 - xmin) * inv_lx);
    int i1 = (int)floorf((bx1 - xmin) * inv_lx);
    int j0 = (int)floorf((by0 - ymin) * inv_ly);
    int j1 = (int)floorf((by1 - ymin) * inv_ly);
    i0 = max(i0, 0);  j0 = max(j0, 0);
    i1 = min(i1, G - 1);  j1 = min(j1, G - 1);

    // Precompute y overlaps (at most 4 cells since dims < 3*ly)
    float oyv[4];
    int nj = j1 - j0 + 1;
    if (nj > 4) nj = 4;   // safety (cannot happen for dims < 3*ly)
    #pragma unroll
    for (int jj = 0; jj < 4; jj++) {
        int j = j0 + jj;
        float gy0 = ymin + (float)j * ly;
        float gy1 = gy0 + ly;
        oyv[jj] = fmaxf(fminf(gy1, by1) - fmaxf(gy0, by0), 0.0f);
    }

    for (int i = i0; i <= i1; i++) {
        float gx0 = xmin + (float)i * lx;
        float gx1 = gx0 + lx;
        float ox = fmaxf(fminf(gx1, bx1) - fmaxf(gx0, bx0), 0.0f);
        if (ox <= 0.0f) continue;
        float sx = scale * ox;
        float* row = field + i * G + j0;
        #pragma unroll
        for (int jj = 0; jj < 4; jj++) {
            if (jj < nj) {
                float v = sx * oyv[jj];
                if (v != 0.0f) atomicAdd(row + jj, v);
            }
        }
    }
}

extern "C" void kernel_launch(void* const* d_in, const int* in_sizes, int n_in,
                              void* d_out, int out_size) {
    const float*  boundary = (const float*)d_in[0];
    const float2* xy       = (const float2*)d_in[1];
    const float2* dims     = (const float2*)d_in[2];
    const float*  cw       = (const float*)d_in[3];
    float* field = (float*)d_out;

    const int n = in_sizes[3];          // charge_weight element count = N_RECTS

    // d_out is poisoned; zero it first.
    zero_field_kernel<<<(out_size + 255) / 256, 256>>>(field, out_size);

    charge_scatter_kernel<<<(n + 255) / 256, 256>>>(boundary, xy, dims, cw, field, n);
}

// round 3
// speedup vs baseline: 1.6517x; 1.6517x over previous
#include <cuda_runtime.h>

// field[i,j] = sum_n w_n * ox_n[i] * oy_n[j] / (lx*ly)
// dims < 3/G per axis  ->  each rect overlaps at most 4 consecutive cells per axis.
// Scatter with global float REDs; 2 threads per rect (each owns a 2-wide j-half).

#define G 256

__global__ void zero_field_kernel4(float4* __restrict__ out, int n4) {
    int i = blockIdx.x * blockDim.x + threadIdx.x;
    if (i < n4) out[i] = make_float4(0.f, 0.f, 0.f, 0.f);
}

__global__ void __launch_bounds__(256) charge_scatter_kernel(
    const float4* __restrict__ boundary,  // [xmin, ymin, xmax, ymax]
    const float2* __restrict__ xy,        // [N]
    const float2* __restrict__ dims,      // [N]
    const float* __restrict__ cw,         // [N]
    float* __restrict__ field,            // [G*G]
    int n)
{
    int t = blockIdx.x * blockDim.x + threadIdx.x;
    int r = t >> 1;          // rect index
    int half = t & 1;        // which 2-column j-half of the footprint
    if (r >= n) return;

    const float4 b = *boundary;
    const float xmin = b.x, ymin = b.y;
    const float lx = (b.z - b.x) * (1.0f / G);
    const float ly = (b.w - b.y) * (1.0f / G);
    const float inv_lx = 1.0f / lx;
    const float inv_ly = 1.0f / ly;

    const float2 p = xy[r];
    const float2 d = dims[r];
    const float bx0 = p.x;
    const float by0 = p.y;
    const float bx1 = bx0 + d.x;
    const float by1 = by0 + d.y;
    const float scale = cw[r] * inv_lx * inv_ly;

    // Footprint cell ranges (clamped; span <= 4 cells per axis since dims < 3/G)
    int i0 = (int)floorf((bx0 - xmin) * inv_lx);
    int j0 = (int)floorf((by0 - ymin) * inv_ly);
    i0 = max(i0, 0);
    j0 = max(j0, 0);

    // This thread's two j cells
    const int jA = j0 + half * 2;

    // y overlaps for the two cells (clamped fmax gives 0 outside footprint)
    float oy0, oy1;
    {
        float gy0 = ymin + (float)jA * ly;
        float gy1 = gy0 + ly;
        oy0 = fmaxf(fminf(gy1, by1) - fmaxf(gy0, by0), 0.0f);
        oy1 = fmaxf(fminf(gy1 + ly, by1) - fmaxf(gy1, by0), 0.0f);
    }
    const bool jA_ok = (jA < G);
    const bool jB_ok = (jA + 1 < G);

    #pragma unroll
    for (int ii = 0; ii < 4; ii++) {
        int i = i0 + ii;
        float gx0 = xmin + (float)i * lx;
        float ox = fmaxf(fminf(gx0 + lx, bx1) - fmaxf(gx0, bx0), 0.0f);
        float sx = scale * ox;
        if (i < G) {
            float* row = field + i * G + jA;
            float v0 = sx * oy0;
            float v1 = sx * oy1;
            if (jA_ok && v0 != 0.0f) atomicAdd(row,     v0);
            if (jB_ok && v1 != 0.0f) atomicAdd(row + 1, v1);
        }
    }
}

extern "C" void kernel_launch(void* const* d_in, const int* in_sizes, int n_in,
                              void* d_out, int out_size) {
    const float4* boundary = (const float4*)d_in[0];
    const float2* xy       = (const float2*)d_in[1];
    const float2* dims     = (const float2*)d_in[2];
    const float*  cw       = (const float*)d_in[3];
    float* field = (float*)d_out;

    const int n = in_sizes[3];          // N_RECTS

    // d_out is poisoned; zero it (vectorized).
    int n4 = out_size / 4;
    zero_field_kernel4<<<(n4 + 255) / 256, 256>>>((float4*)field, n4);

    // 2 threads per rect
    int threads_total = 2 * n;
    charge_scatter_kernel<<<(threads_total + 255) / 256, 256>>>(
        boundary, xy, dims, cw, field, n);
}